// round 16
// baseline (speedup 1.0000x reference)
#include <cuda_runtime.h>
#include <cuda_fp16.h>
#include <math.h>

#define NN 100000
#define EE 1600000
#define GG 512

// ---------------- scratch (device globals; no allocation allowed) ----------
__device__ __align__(16) unsigned g_hbA[NN * 64];  // half2 activations ping
__device__ __align__(16) unsigned g_hbB[NN * 64];  // half2 activations pong
__device__ __align__(16) unsigned g_hbT[NN * 32];  // L5 gemm output (half2, 64w)
__device__ float g_x2[NN * 2];   // dinv-scaled input features
__device__ float g_a2[NN * 2];   // aggregated 2-wide features
__device__ float g_dinv[NN];
__device__ int   g_degi[NN];
__device__ int   g_off[NN];
__device__ int   g_cursor[NN];
__device__ int   g_csrc[EE];
__device__ int   g_ctr;
__device__ unsigned g_pool[GG * 64];

// ---------------- half helpers ----------------------------------------------
__device__ __forceinline__ float2 h2f(unsigned v) {
    return __half22float2(*(__half2*)&v);
}
__device__ __forceinline__ unsigned f2h(float a, float b) {
    __half2 p = __floats2half2_rn(a, b);
    return *(unsigned*)&p;
}

// ---------------- CSR build --------------------------------------------------
__global__ void __launch_bounds__(256) k_zero() {
    int i = blockIdx.x * blockDim.x + threadIdx.x;
    if (i < NN) g_degi[i] = 0;
    if (i < GG * 64) g_pool[i] = 0u;
    if (i == 0) g_ctr = 0;
}
__global__ void __launch_bounds__(256) k_deg(const int* __restrict__ dst) {
    int e = blockIdx.x * blockDim.x + threadIdx.x;
    if (e < EE) atomicAdd(&g_degi[dst[e]], 1);
}
__global__ void __launch_bounds__(256) k_prep(const float* __restrict__ x) {
    int i = blockIdx.x * 256 + threadIdx.x;
    int lane = threadIdx.x & 31;
    int w = threadIdx.x >> 5;
    int v = (i < NN) ? g_degi[i] : 0;
    if (i < NN) {
        float di = rsqrtf((float)v + 1.0f);  // +1 self loop
        g_dinv[i] = di;
        g_x2[i * 2 + 0] = di * x[i * 2 + 0];
        g_x2[i * 2 + 1] = di * x[i * 2 + 1];
    }
    int xs = v;
#pragma unroll
    for (int o = 1; o < 32; o <<= 1) {
        int y = __shfl_up_sync(0xffffffffu, xs, o);
        if (lane >= o) xs += y;
    }
    __shared__ int ws[8];
    __shared__ int base;
    if (lane == 31) ws[w] = xs;
    __syncthreads();
    if (w == 0) {
        int s = (lane < 8) ? ws[lane] : 0;
#pragma unroll
        for (int o = 1; o < 8; o <<= 1) {
            int y = __shfl_up_sync(0xffffffffu, s, o);
            if (lane >= o) s += y;
        }
        if (lane < 8) ws[lane] = s;
    }
    __syncthreads();
    if (threadIdx.x == 0) base = atomicAdd(&g_ctr, ws[7]);
    int excl = xs - v + ((w > 0) ? ws[w - 1] : 0);
    __syncthreads();
    if (i < NN) {
        int off = base + excl;
        g_off[i] = off;
        g_cursor[i] = off;
    }
}
__global__ void __launch_bounds__(256) k_fill(const int* __restrict__ src,
                                              const int* __restrict__ dst) {
    int e = blockIdx.x * blockDim.x + threadIdx.x;
    if (e < EE) {
        int pos = atomicAdd(&g_cursor[dst[e]], 1);
        g_csrc[pos] = src[e];
    }
}

// ---------------- L1 aggregation (DI=2, fp32) -------------------------------
__global__ void __launch_bounds__(256) k_aggr_pre2() {
    int n = blockIdx.x * blockDim.x + threadIdx.x;
    if (n >= NN) return;
    const float2* hh = (const float2*)g_x2;
    float2 acc = hh[n];
    int e = g_off[n];
    int r1 = e + g_degi[n];
    for (; e < r1; e++) {
        float2 v = __ldg(&hh[g_csrc[e]]);
        acc.x += v.x;
        acc.y += v.y;
    }
    float di = g_dinv[n];
    g_a2[n * 2 + 0] = di * acc.x;
    g_a2[n * 2 + 1] = di * acc.y;
}

// ---------------- epilogue helper -------------------------------------------
__device__ __forceinline__ float gelu_bn(float x, float bb, float gg, float be, bool bn) {
    x = x + bb;
    if (bn) x = x * (gg * 0.99999500003749973f) + be;
    return 0.5f * x * (1.0f + erff(x * 0.70710678118654752f));
}

// ---------------- L1: out = epi(a @ W1), half output ------------------------
__global__ void __launch_bounds__(256) k_l1(const float* __restrict__ W,
                                            const float* __restrict__ b,
                                            const float* __restrict__ gam,
                                            const float* __restrict__ bet) {
    int lane = threadIdx.x & 31;
    int warp = threadIdx.x >> 5;
    int n = blockIdx.x * 8 + warp;
    if (n >= NN) return;
    float2 a = ((const float2*)g_a2)[n];
    float2 w0 = __ldg(&((const float2*)W)[lane]);
    float2 w1 = __ldg(&((const float2*)(W + 64))[lane]);
    float2 bb = __ldg(&((const float2*)b)[lane]);
    float2 gg = __ldg(&((const float2*)gam)[lane]);
    float2 be = __ldg(&((const float2*)bet)[lane]);
    float di = g_dinv[n];
    float x0 = a.x * w0.x + a.y * w1.x;
    float x1 = a.x * w0.y + a.y * w1.y;
    x0 = di * gelu_bn(x0, bb.x, gg.x, be.x, true);
    x1 = di * gelu_bn(x1, bb.y, gg.y, be.y, true);
    g_hbA[n * 32 + lane] = f2h(x0, x1);
}

// ---------------- FUSED: aggregate(DI) -> smem -> HMMA -> epi -> half out ---
// Block 256 thr / 8 warps; warp w aggregates+computes nodes [w*16, w*16+16).
template <int DI, int DO, bool BN>
__global__ void __launch_bounds__(256) k_fused(const unsigned* __restrict__ in,
                                               unsigned* __restrict__ outp,
                                               const float* __restrict__ W,
                                               const float* __restrict__ b,
                                               const float* __restrict__ gam,
                                               const float* __restrict__ bet) {
    constexpr int MT = 128;
    constexpr int SD = DI + 8;
    constexpr int SK = 40;
    constexpr int NT = DO / 8;
    __shared__ __align__(16) __half As[MT * SD];
    __shared__ __align__(16) __half Bs[DO * SK];

    int tid = threadIdx.x;
    int lane = tid & 31;
    int warp = tid >> 5;
    int gid = lane >> 2;
    int tig = lane & 3;
    int n0 = blockIdx.x * MT;

    // ---- phase 1: aggregate this warp's 16 rows into As (fp16) ----
    for (int wn = 0; wn < 16; wn++) {
        int nl = warp * 16 + wn;
        int n = n0 + nl;
        if (n >= NN) n = NN - 1;  // tail: compute garbage, never stored
        int e = g_off[n];
        int r1 = e + g_degi[n];
        float di = g_dinv[n];
        if (DI == 64) {
            float2 f = h2f(__ldg(&in[n * 32 + lane]));
            float ax = f.x, ay = f.y, bx = 0.f, by = 0.f;
            for (; e + 3 < r1; e += 4) {
                unsigned v0 = __ldg(&in[g_csrc[e] * 32 + lane]);
                unsigned v1 = __ldg(&in[g_csrc[e + 1] * 32 + lane]);
                unsigned v2 = __ldg(&in[g_csrc[e + 2] * 32 + lane]);
                unsigned v3 = __ldg(&in[g_csrc[e + 3] * 32 + lane]);
                float2 f0 = h2f(v0), f1 = h2f(v1), f2 = h2f(v2), f3 = h2f(v3);
                ax += f0.x + f2.x; ay += f0.y + f2.y;
                bx += f1.x + f3.x; by += f1.y + f3.y;
            }
            for (; e < r1; e++) {
                float2 f0 = h2f(__ldg(&in[g_csrc[e] * 32 + lane]));
                ax += f0.x; ay += f0.y;
            }
            *(unsigned*)&As[nl * SD + 2 * lane] = f2h(di * (ax + bx), di * (ay + by));
        } else {  // DI == 128
            const uint2* H = (const uint2*)in;
            uint2 sv = __ldg(&H[n * 32 + lane]);
            float2 fa = h2f(sv.x), fb = h2f(sv.y);
            float a0 = fa.x, a1 = fa.y, a2 = fb.x, a3 = fb.y;
            float b0 = 0.f, b1 = 0.f, b2 = 0.f, b3 = 0.f;
            for (; e + 1 < r1; e += 2) {
                uint2 v0 = __ldg(&H[g_csrc[e] * 32 + lane]);
                uint2 v1 = __ldg(&H[g_csrc[e + 1] * 32 + lane]);
                float2 p;
                p = h2f(v0.x); a0 += p.x; a1 += p.y;
                p = h2f(v0.y); a2 += p.x; a3 += p.y;
                p = h2f(v1.x); b0 += p.x; b1 += p.y;
                p = h2f(v1.y); b2 += p.x; b3 += p.y;
            }
            if (e < r1) {
                uint2 v0 = __ldg(&H[g_csrc[e] * 32 + lane]);
                float2 p;
                p = h2f(v0.x); a0 += p.x; a1 += p.y;
                p = h2f(v0.y); a2 += p.x; a3 += p.y;
            }
            *(unsigned*)&As[nl * SD + 4 * lane] = f2h(di * (a0 + b0), di * (a1 + b1));
            *(unsigned*)&As[nl * SD + 4 * lane + 2] = f2h(di * (a2 + b2), di * (a3 + b3));
        }
    }

    // ---- phase 2: HMMA ----
    float C[NT][4];
#pragma unroll
    for (int t = 0; t < NT; t++) {
        C[t][0] = 0.f; C[t][1] = 0.f; C[t][2] = 0.f; C[t][3] = 0.f;
    }

    for (int k0 = 0; k0 < DI; k0 += 32) {
        __syncthreads();  // As ready (first iter) / prior Bs consumed
        for (int it = tid; it < DO * 32; it += 256) {
            int nn = it % DO;
            int kk = it / DO;
            Bs[nn * SK + kk] = __float2half(W[(k0 + kk) * DO + nn]);
        }
        __syncthreads();
#pragma unroll
        for (int ks = 0; ks < 2; ks++) {
            int ka = k0 + ks * 16 + 2 * tig;
            int ar = warp * 16 + gid;
            unsigned a0 = *(const unsigned*)&As[ar * SD + ka];
            unsigned a1 = *(const unsigned*)&As[(ar + 8) * SD + ka];
            unsigned a2 = *(const unsigned*)&As[ar * SD + ka + 8];
            unsigned a3 = *(const unsigned*)&As[(ar + 8) * SD + ka + 8];
            int kb = ks * 16 + 2 * tig;
#pragma unroll
            for (int nt = 0; nt < NT; nt++) {
                int nn = nt * 8 + gid;
                unsigned b0 = *(const unsigned*)&Bs[nn * SK + kb];
                unsigned b1 = *(const unsigned*)&Bs[nn * SK + kb + 8];
                asm volatile(
                    "mma.sync.aligned.m16n8k16.row.col.f32.f16.f16.f32 "
                    "{%0,%1,%2,%3}, {%4,%5,%6,%7}, {%8,%9}, {%0,%1,%2,%3};"
                    : "+f"(C[nt][0]), "+f"(C[nt][1]), "+f"(C[nt][2]), "+f"(C[nt][3])
                    : "r"(a0), "r"(a1), "r"(a2), "r"(a3), "r"(b0), "r"(b1));
            }
        }
    }

    // ---- epilogue: bias (+BN) + GELU + dinv -> half out ----
    int na = n0 + warp * 16 + gid;
    int nb = na + 8;
#pragma unroll
    for (int nt = 0; nt < NT; nt++) {
        int col = nt * 8 + 2 * tig;
        float2 bb = *(const float2*)&b[col];
        float2 gg = BN ? *(const float2*)&gam[col] : make_float2(0.f, 0.f);
        float2 be = BN ? *(const float2*)&bet[col] : make_float2(0.f, 0.f);
#pragma unroll
        for (int half_ = 0; half_ < 2; half_++) {
            int n = half_ ? nb : na;
            if (n < NN) {
                float di = g_dinv[n];
                float v0 = di * gelu_bn(C[nt][half_ * 2 + 0], bb.x, gg.x, be.x, BN);
                float v1 = di * gelu_bn(C[nt][half_ * 2 + 1], bb.y, gg.y, be.y, BN);
                outp[n * (DO / 2) + (col >> 1)] = f2h(v0, v1);
            }
        }
    }
}

// ---------------- L5 GEMM: half in (copy-staged), raw half out --------------
__global__ void __launch_bounds__(256) k_mma5(const unsigned* __restrict__ in,
                                              const float* __restrict__ W) {
    constexpr int DI = 128;
    constexpr int DO = 64;
    constexpr int MT = 128;
    constexpr int SD = DI + 8;
    constexpr int SK = 40;
    constexpr int NT = DO / 8;
    __shared__ __align__(16) __half As[MT * SD];
    __shared__ __align__(16) __half Bs[DO * SK];

    int tid = threadIdx.x;
    int lane = tid & 31;
    int warp = tid >> 5;
    int gid = lane >> 2;
    int tig = lane & 3;
    int n0 = blockIdx.x * MT;

    // stage A: copy u32 (half2) rows
    for (int it = tid; it < MT * (DI / 2); it += 256) {
        int nl = it / (DI / 2);
        int c = it % (DI / 2);
        int n = n0 + nl;
        if (n >= NN) n = NN - 1;
        *(unsigned*)&As[nl * SD + 2 * c] = __ldg(&in[n * (DI / 2) + c]);
    }

    float C[NT][4];
#pragma unroll
    for (int t = 0; t < NT; t++) {
        C[t][0] = 0.f; C[t][1] = 0.f; C[t][2] = 0.f; C[t][3] = 0.f;
    }

    for (int k0 = 0; k0 < DI; k0 += 32) {
        __syncthreads();
        for (int it = tid; it < DO * 32; it += 256) {
            int nn = it % DO;
            int kk = it / DO;
            Bs[nn * SK + kk] = __float2half(W[(k0 + kk) * DO + nn]);
        }
        __syncthreads();
#pragma unroll
        for (int ks = 0; ks < 2; ks++) {
            int ka = k0 + ks * 16 + 2 * tig;
            int ar = warp * 16 + gid;
            unsigned a0 = *(const unsigned*)&As[ar * SD + ka];
            unsigned a1 = *(const unsigned*)&As[(ar + 8) * SD + ka];
            unsigned a2 = *(const unsigned*)&As[ar * SD + ka + 8];
            unsigned a3 = *(const unsigned*)&As[(ar + 8) * SD + ka + 8];
            int kb = ks * 16 + 2 * tig;
#pragma unroll
            for (int nt = 0; nt < NT; nt++) {
                int nn = nt * 8 + gid;
                unsigned b0 = *(const unsigned*)&Bs[nn * SK + kb];
                unsigned b1 = *(const unsigned*)&Bs[nn * SK + kb + 8];
                asm volatile(
                    "mma.sync.aligned.m16n8k16.row.col.f32.f16.f16.f32 "
                    "{%0,%1,%2,%3}, {%4,%5,%6,%7}, {%8,%9}, {%0,%1,%2,%3};"
                    : "+f"(C[nt][0]), "+f"(C[nt][1]), "+f"(C[nt][2]), "+f"(C[nt][3])
                    : "r"(a0), "r"(a1), "r"(a2), "r"(a3), "r"(b0), "r"(b1));
            }
        }
    }

    int na = n0 + warp * 16 + gid;
    int nb = na + 8;
#pragma unroll
    for (int nt = 0; nt < NT; nt++) {
        int col = nt * 8 + 2 * tig;
#pragma unroll
        for (int half_ = 0; half_ < 2; half_++) {
            int n = half_ ? nb : na;
            if (n < NN)
                g_hbT[n * 32 + (col >> 1)] =
                    f2h(C[nt][half_ * 2 + 0], C[nt][half_ * 2 + 1]);
        }
    }
}

// ---------------- pool encoding ---------------------------------------------
__device__ __forceinline__ unsigned fenc(float x) {
    unsigned u = __float_as_uint(x);
    return (u & 0x80000000u) ? ~u : (u | 0x80000000u);
}
__device__ __forceinline__ float fdec(unsigned u) {
    return (u & 0x80000000u) ? __uint_as_float(u & 0x7fffffffu) : __uint_as_float(~u);
}

// ---------------- L5: aggregate (half) + bias + BN + GELU + pool ------------
__global__ void __launch_bounds__(256) k_aggr_post(const float* __restrict__ b,
                                                   const float* __restrict__ gam,
                                                   const float* __restrict__ bet,
                                                   const int* __restrict__ batch) {
    int lane = threadIdx.x & 31;
    int warp = threadIdx.x >> 5;
    int n = blockIdx.x * 8 + warp;
    if (n >= NN) return;
    float2 f = h2f(g_hbT[n * 32 + lane]);
    float ax = f.x, ay = f.y, bx = 0.f, by = 0.f;
    int e = g_off[n];
    int r1 = e + g_degi[n];
    for (; e + 3 < r1; e += 4) {
        unsigned v0 = __ldg(&g_hbT[g_csrc[e] * 32 + lane]);
        unsigned v1 = __ldg(&g_hbT[g_csrc[e + 1] * 32 + lane]);
        unsigned v2 = __ldg(&g_hbT[g_csrc[e + 2] * 32 + lane]);
        unsigned v3 = __ldg(&g_hbT[g_csrc[e + 3] * 32 + lane]);
        float2 f0 = h2f(v0), f1 = h2f(v1), f2 = h2f(v2), f3 = h2f(v3);
        ax += f0.x + f2.x; ay += f0.y + f2.y;
        bx += f1.x + f3.x; by += f1.y + f3.y;
    }
    for (; e < r1; e++) {
        float2 f0 = h2f(__ldg(&g_hbT[g_csrc[e] * 32 + lane]));
        ax += f0.x; ay += f0.y;
    }
    float di = g_dinv[n];
    int gb = batch[n];
    float2 bb = __ldg(&((const float2*)b)[lane]);
    float2 gg = __ldg(&((const float2*)gam)[lane]);
    float2 be = __ldg(&((const float2*)bet)[lane]);
    float v0 = gelu_bn(di * (ax + bx), bb.x, gg.x, be.x, true);
    float v1 = gelu_bn(di * (ay + by), bb.y, gg.y, be.y, true);
    atomicMax(&g_pool[gb * 64 + 2 * lane + 0], fenc(v0));
    atomicMax(&g_pool[gb * 64 + 2 * lane + 1], fenc(v1));
}

// ---------------- MLP head --------------------------------------------------
__global__ void __launch_bounds__(256) k_head(const float* __restrict__ lw1,
                                              const float* __restrict__ lb1,
                                              const float* __restrict__ lw2,
                                              const float* __restrict__ lb2,
                                              float* __restrict__ out) {
    int g = blockIdx.x * blockDim.x + threadIdx.x;
    if (g < GG) {
        float p[64];
#pragma unroll
        for (int d = 0; d < 64; d++) p[d] = fdec(g_pool[g * 64 + d]);
        float o0 = lb2[0];
        float o1 = lb2[1];
#pragma unroll
        for (int j = 0; j < 10; j++) {
            float hj = lb1[j];
#pragma unroll
            for (int d = 0; d < 64; d++) hj += p[d] * lw1[d * 10 + j];
            o0 += hj * lw2[j * 2 + 0];
            o1 += hj * lw2[j * 2 + 1];
        }
        out[g * 2 + 0] = o0;
        out[g * 2 + 1] = o1;
    }
}

extern "C" void kernel_launch(void* const* d_in, const int* in_sizes, int n_in,
                              void* d_out, int out_size) {
    const float* x = (const float*)d_in[0];
    const int* ei = (const int*)d_in[1];
    const int* src = ei;
    const int* dst = ei + EE;
    const int* batch = (const int*)d_in[2];
    const float* W1 = (const float*)d_in[3];
    const float* b1 = (const float*)d_in[4];
    const float* W2 = (const float*)d_in[5];
    const float* b2 = (const float*)d_in[6];
    const float* W3 = (const float*)d_in[7];
    const float* b3 = (const float*)d_in[8];
    const float* W4 = (const float*)d_in[9];
    const float* b4 = (const float*)d_in[10];
    const float* W5 = (const float*)d_in[11];
    const float* b5 = (const float*)d_in[12];
    const float* g1 = (const float*)d_in[13];
    const float* be1 = (const float*)d_in[14];
    const float* g2 = (const float*)d_in[15];
    const float* be2 = (const float*)d_in[16];
    const float* g3 = (const float*)d_in[17];
    const float* be3 = (const float*)d_in[18];
    const float* lw1 = (const float*)d_in[19];
    const float* lb1 = (const float*)d_in[20];
    const float* lw2 = (const float*)d_in[21];
    const float* lb2 = (const float*)d_in[22];
    float* out = (float*)d_out;

    unsigned* hbA = nullptr;
    unsigned* hbB = nullptr;
    cudaGetSymbolAddress((void**)&hbA, g_hbA);
    cudaGetSymbolAddress((void**)&hbB, g_hbB);

    // CSR build
    k_zero<<<(NN + 255) / 256, 256>>>();
    k_deg<<<(EE + 255) / 256, 256>>>(dst);
    k_prep<<<(NN + 255) / 256, 256>>>(x);
    k_fill<<<(EE + 255) / 256, 256>>>(src, dst);

    const int GB = (NN + 127) / 128;

    // L1: aggregate (DI=2, fp32) then tiny GEMM 2->64 + BN + GELU + dinv -> hbA
    k_aggr_pre2<<<(NN + 255) / 256, 256>>>();
    k_l1<<<(NN + 7) / 8, 256>>>(W1, b1, g1, be1);
    // L2: fused aggregate(64)+GEMM 64->64 + GELU + dinv : hbA -> hbB
    k_fused<64, 64, false><<<GB, 256>>>(hbA, hbB, W2, b2, nullptr, nullptr);
    // L3: fused aggregate(64)+GEMM 64->128 + BN + GELU + dinv : hbB -> hbA
    k_fused<64, 128, true><<<GB, 256>>>(hbB, hbA, W3, b3, g2, be2);
    // L4: fused aggregate(128)+GEMM 128->128 + GELU + dinv : hbA -> hbB
    k_fused<128, 128, false><<<GB, 256>>>(hbA, hbB, W4, b4, nullptr, nullptr);
    // L5: GEMM 128->64 (half in, raw half out) then aggregate+bias+BN+GELU+pool
    k_mma5<<<GB, 256>>>(hbB, W5);
    k_aggr_post<<<(NN + 7) / 8, 256>>>(b5, g3, be3, batch);

    k_head<<<2, 256>>>(lw1, lb1, lw2, lb2, out);
}

// round 17
// speedup vs baseline: 1.1780x; 1.1780x over previous
#include <cuda_runtime.h>
#include <cuda_fp16.h>
#include <math.h>

#define NN 100000
#define EE 1600000
#define GG 512

// ---------------- scratch (device globals; no allocation allowed) ----------
__device__ float g_h[NN * 128];              // fp32 activations (L1-in 2wide, L4 out)
__device__ float g_a[NN * 128];              // aggregated (pre-GEMM) features, fp32
__device__ __align__(16) unsigned g_hh[NN * 64];  // half2-packed activations for gathers
__device__ __align__(16) __half g_wh[36864];      // preconverted weights, [n][k] layout
__device__ float g_dinv[NN];
__device__ int   g_degi[NN];
__device__ int   g_off[NN];
__device__ int   g_cursor[NN];
__device__ int   g_csrc[EE];
__device__ int   g_ctr;
__device__ unsigned g_pool[GG * 64];

// ---------------- half helpers ----------------------------------------------
__device__ __forceinline__ float2 h2f(unsigned v) {
    return __half22float2(*(__half2*)&v);
}
__device__ __forceinline__ unsigned f2h(float a, float b) {
    __half2 p = __floats2half2_rn(a, b);
    return *(unsigned*)&p;
}

// ---------------- CSR build --------------------------------------------------
__global__ void __launch_bounds__(256) k_zero() {
    int i = blockIdx.x * blockDim.x + threadIdx.x;
    if (i < NN) g_degi[i] = 0;
    if (i < GG * 64) g_pool[i] = 0u;
    if (i == 0) g_ctr = 0;
}
__global__ void __launch_bounds__(256) k_deg(const int* __restrict__ dst) {
    int e = blockIdx.x * blockDim.x + threadIdx.x;
    if (e < EE) atomicAdd(&g_degi[dst[e]], 1);
}
__global__ void __launch_bounds__(256) k_prep(const float* __restrict__ x) {
    int i = blockIdx.x * 256 + threadIdx.x;
    int lane = threadIdx.x & 31;
    int w = threadIdx.x >> 5;
    int v = (i < NN) ? g_degi[i] : 0;
    if (i < NN) {
        float di = rsqrtf((float)v + 1.0f);  // +1 self loop
        g_dinv[i] = di;
        g_h[i * 2 + 0] = di * x[i * 2 + 0];
        g_h[i * 2 + 1] = di * x[i * 2 + 1];
    }
    int xs = v;
#pragma unroll
    for (int o = 1; o < 32; o <<= 1) {
        int y = __shfl_up_sync(0xffffffffu, xs, o);
        if (lane >= o) xs += y;
    }
    __shared__ int ws[8];
    __shared__ int base;
    if (lane == 31) ws[w] = xs;
    __syncthreads();
    if (w == 0) {
        int s = (lane < 8) ? ws[lane] : 0;
#pragma unroll
        for (int o = 1; o < 8; o <<= 1) {
            int y = __shfl_up_sync(0xffffffffu, s, o);
            if (lane >= o) s += y;
        }
        if (lane < 8) ws[lane] = s;
    }
    __syncthreads();
    if (threadIdx.x == 0) base = atomicAdd(&g_ctr, ws[7]);
    int excl = xs - v + ((w > 0) ? ws[w - 1] : 0);
    __syncthreads();
    if (i < NN) {
        int off = base + excl;
        g_off[i] = off;
        g_cursor[i] = off;
    }
}
__global__ void __launch_bounds__(256) k_fill(const int* __restrict__ src,
                                              const int* __restrict__ dst) {
    int e = blockIdx.x * blockDim.x + threadIdx.x;
    if (e < EE) {
        int pos = atomicAdd(&g_cursor[dst[e]], 1);
        g_csrc[pos] = src[e];
    }
}

// ---------------- weight preconversion: fp32 [k][n] -> fp16 [n][k] ----------
// segments: W2 @0 (64x64), W3 @4096 (128n x 64k), W4 @12288 (128x128),
//           W5 @28672 (64n x 128k)
__global__ void __launch_bounds__(256) k_wconv(const float* __restrict__ W2,
                                               const float* __restrict__ W3,
                                               const float* __restrict__ W4,
                                               const float* __restrict__ W5) {
    int i = blockIdx.x * 256 + threadIdx.x;
    if (i < 4096) {
        int nn = i >> 6, kk = i & 63;
        g_wh[i] = __float2half(W2[kk * 64 + nn]);
    } else if (i < 12288) {
        int j = i - 4096;
        int nn = j >> 6, kk = j & 63;
        g_wh[i] = __float2half(W3[kk * 128 + nn]);
    } else if (i < 28672) {
        int j = i - 12288;
        int nn = j >> 7, kk = j & 127;
        g_wh[i] = __float2half(W4[kk * 128 + nn]);
    } else if (i < 36864) {
        int j = i - 28672;
        int nn = j >> 7, kk = j & 127;
        g_wh[i] = __float2half(W5[kk * 64 + nn]);
    }
}

// ---------------- aggregation (fp16 gathers, fp32 accumulate) ---------------
__global__ void __launch_bounds__(256) k_aggr_pre2() {
    int n = blockIdx.x * blockDim.x + threadIdx.x;
    if (n >= NN) return;
    const float2* hh = (const float2*)g_h;
    float2 acc = hh[n];
    int e = g_off[n];
    int r1 = e + g_degi[n];
    for (; e < r1; e++) {
        float2 v = __ldg(&hh[g_csrc[e]]);
        acc.x += v.x;
        acc.y += v.y;
    }
    float di = g_dinv[n];
    g_a[n * 2 + 0] = di * acc.x;
    g_a[n * 2 + 1] = di * acc.y;
}

__global__ void __launch_bounds__(256) k_aggr64h(float* __restrict__ outp) {
    int lane = threadIdx.x & 31;
    int warp = threadIdx.x >> 5;
    int n = blockIdx.x * 8 + warp;
    if (n >= NN) return;
    float2 f = h2f(g_hh[n * 32 + lane]);   // self term
    float ax = f.x, ay = f.y, bx = 0.f, by = 0.f;
    int e = g_off[n];
    int r1 = e + g_degi[n];
    for (; e + 3 < r1; e += 4) {
        unsigned v0 = __ldg(&g_hh[g_csrc[e] * 32 + lane]);
        unsigned v1 = __ldg(&g_hh[g_csrc[e + 1] * 32 + lane]);
        unsigned v2 = __ldg(&g_hh[g_csrc[e + 2] * 32 + lane]);
        unsigned v3 = __ldg(&g_hh[g_csrc[e + 3] * 32 + lane]);
        float2 f0 = h2f(v0), f1 = h2f(v1), f2 = h2f(v2), f3 = h2f(v3);
        ax += f0.x + f2.x; ay += f0.y + f2.y;
        bx += f1.x + f3.x; by += f1.y + f3.y;
    }
    for (; e < r1; e++) {
        float2 f0 = h2f(__ldg(&g_hh[g_csrc[e] * 32 + lane]));
        ax += f0.x; ay += f0.y;
    }
    float di = g_dinv[n];
    ((float2*)outp)[n * 32 + lane] = make_float2(di * (ax + bx), di * (ay + by));
}

__global__ void __launch_bounds__(256) k_aggr128h() {
    int lane = threadIdx.x & 31;
    int warp = threadIdx.x >> 5;
    int n = blockIdx.x * 8 + warp;
    if (n >= NN) return;
    const uint2* H = (const uint2*)g_hh;
    uint2 sv = H[n * 32 + lane];
    float2 fa = h2f(sv.x), fb = h2f(sv.y);
    float a0 = fa.x, a1 = fa.y, a2 = fb.x, a3 = fb.y;
    float b0 = 0.f, b1 = 0.f, b2 = 0.f, b3 = 0.f;
    int e = g_off[n];
    int r1 = e + g_degi[n];
    for (; e + 3 < r1; e += 4) {
        uint2 v0 = __ldg(&H[g_csrc[e] * 32 + lane]);
        uint2 v1 = __ldg(&H[g_csrc[e + 1] * 32 + lane]);
        uint2 v2 = __ldg(&H[g_csrc[e + 2] * 32 + lane]);
        uint2 v3 = __ldg(&H[g_csrc[e + 3] * 32 + lane]);
        float2 p;
        p = h2f(v0.x); a0 += p.x; a1 += p.y;
        p = h2f(v0.y); a2 += p.x; a3 += p.y;
        p = h2f(v1.x); b0 += p.x; b1 += p.y;
        p = h2f(v1.y); b2 += p.x; b3 += p.y;
        p = h2f(v2.x); a0 += p.x; a1 += p.y;
        p = h2f(v2.y); a2 += p.x; a3 += p.y;
        p = h2f(v3.x); b0 += p.x; b1 += p.y;
        p = h2f(v3.y); b2 += p.x; b3 += p.y;
    }
    for (; e < r1; e++) {
        uint2 v0 = __ldg(&H[g_csrc[e] * 32 + lane]);
        float2 p;
        p = h2f(v0.x); a0 += p.x; a1 += p.y;
        p = h2f(v0.y); a2 += p.x; a3 += p.y;
    }
    float di = g_dinv[n];
    ((float4*)g_a)[n * 32 + lane] = make_float4(di * (a0 + b0), di * (a1 + b1),
                                                di * (a2 + b2), di * (a3 + b3));
}

// ---------------- epilogue helper -------------------------------------------
__device__ __forceinline__ float gelu_bn(float x, float bb, float gg, float be, bool bn) {
    x = x + bb;
    if (bn) x = x * (gg * 0.99999500003749973f) + be;
    return 0.5f * x * (1.0f + erff(x * 0.70710678118654752f));
}

// ---------------- L1: out = epi(a @ W1), half output ------------------------
__global__ void __launch_bounds__(256) k_l1(const float* __restrict__ W,
                                            const float* __restrict__ b,
                                            const float* __restrict__ gam,
                                            const float* __restrict__ bet) {
    int lane = threadIdx.x & 31;
    int warp = threadIdx.x >> 5;
    int n = blockIdx.x * 8 + warp;
    if (n >= NN) return;
    float2 a = ((const float2*)g_a)[n];
    float2 w0 = __ldg(&((const float2*)W)[lane]);
    float2 w1 = __ldg(&((const float2*)(W + 64))[lane]);
    float2 bb = __ldg(&((const float2*)b)[lane]);
    float2 gg = __ldg(&((const float2*)gam)[lane]);
    float2 be = __ldg(&((const float2*)bet)[lane]);
    float di = g_dinv[n];
    float x0 = a.x * w0.x + a.y * w1.x;
    float x1 = a.x * w0.y + a.y * w1.y;
    x0 = di * gelu_bn(x0, bb.x, gg.x, be.x, true);
    x1 = di * gelu_bn(x1, bb.y, gg.y, be.y, true);
    g_hh[n * 32 + lane] = f2h(x0, x1);
}

// ---------------- tensor-core GEMM: mma.sync m16n8k16 f16f16f32 -------------
// Wh: preconverted fp16 weights, [n][k] layout (k-contiguous). Bs staged via uint4.
template <int DI, int DO, bool EPI, bool BN, bool OUTH>
__global__ void __launch_bounds__(256) k_mma(const float* __restrict__ h,
                                             const __half* __restrict__ Wh,
                                             const float* __restrict__ b,
                                             const float* __restrict__ gam,
                                             const float* __restrict__ bet) {
    constexpr int MT = 128;
    constexpr int SD = DI + 8;   // As row stride (halves)
    constexpr int SK = 40;       // Bs row stride (halves); 80B keeps 16B alignment
    constexpr int NT = DO / 8;
    __shared__ __align__(16) __half As[MT * SD];
    __shared__ __align__(16) __half Bs[DO * SK];

    int tid = threadIdx.x;
    int lane = tid & 31;
    int warp = tid >> 5;
    int gid = lane >> 2;
    int tig = lane & 3;
    int n0 = blockIdx.x * MT;

    // stage A: [node][k] fp32 -> half, row-major
    for (int it = tid; it < MT * (DI / 4); it += 256) {
        int nl = it / (DI / 4);
        int c4 = it % (DI / 4);
        int n = n0 + nl;
        if (n >= NN) n = NN - 1;
        float4 v = __ldg((const float4*)&h[n * DI + 4 * c4]);
        *(unsigned*)&As[nl * SD + 4 * c4] = f2h(v.x, v.y);
        *(unsigned*)&As[nl * SD + 4 * c4 + 2] = f2h(v.z, v.w);
    }

    float C[NT][4];
#pragma unroll
    for (int t = 0; t < NT; t++) {
        C[t][0] = 0.f; C[t][1] = 0.f; C[t][2] = 0.f; C[t][3] = 0.f;
    }

    for (int k0 = 0; k0 < DI; k0 += 32) {
        __syncthreads();  // As ready (first iter) / prior slab consumed
        // stage W slab via vector copies: 32 halves = 4 uint4 per n-row
        for (int it = tid; it < DO * 4; it += 256) {
            int nn = it >> 2;
            int q = it & 3;
            *(uint4*)&Bs[nn * SK + q * 8] = *(const uint4*)&Wh[nn * DI + k0 + q * 8];
        }
        __syncthreads();
#pragma unroll
        for (int ks = 0; ks < 2; ks++) {
            int ka = k0 + ks * 16 + 2 * tig;
            int ar = warp * 16 + gid;
            unsigned a0 = *(const unsigned*)&As[ar * SD + ka];
            unsigned a1 = *(const unsigned*)&As[(ar + 8) * SD + ka];
            unsigned a2 = *(const unsigned*)&As[ar * SD + ka + 8];
            unsigned a3 = *(const unsigned*)&As[(ar + 8) * SD + ka + 8];
            int kb = ks * 16 + 2 * tig;
#pragma unroll
            for (int nt = 0; nt < NT; nt++) {
                int nn = nt * 8 + gid;
                unsigned b0 = *(const unsigned*)&Bs[nn * SK + kb];
                unsigned b1 = *(const unsigned*)&Bs[nn * SK + kb + 8];
                asm volatile(
                    "mma.sync.aligned.m16n8k16.row.col.f32.f16.f16.f32 "
                    "{%0,%1,%2,%3}, {%4,%5,%6,%7}, {%8,%9}, {%0,%1,%2,%3};"
                    : "+f"(C[nt][0]), "+f"(C[nt][1]), "+f"(C[nt][2]), "+f"(C[nt][3])
                    : "r"(a0), "r"(a1), "r"(a2), "r"(a3), "r"(b0), "r"(b1));
            }
        }
    }

    int na = n0 + warp * 16 + gid;
    int nb = na + 8;
#pragma unroll
    for (int nt = 0; nt < NT; nt++) {
        int col = nt * 8 + 2 * tig;
        float2 bb = EPI ? *(const float2*)&b[col] : make_float2(0.f, 0.f);
        float2 gg = (EPI && BN) ? *(const float2*)&gam[col] : make_float2(0.f, 0.f);
        float2 be = (EPI && BN) ? *(const float2*)&bet[col] : make_float2(0.f, 0.f);
#pragma unroll
        for (int half_ = 0; half_ < 2; half_++) {
            int n = half_ ? nb : na;
            float c0 = C[nt][half_ * 2 + 0];
            float c1 = C[nt][half_ * 2 + 1];
            if (n < NN) {
                if (EPI) {
                    float di = g_dinv[n];
                    float v0 = di * gelu_bn(c0, bb.x, gg.x, be.x, BN);
                    float v1 = di * gelu_bn(c1, bb.y, gg.y, be.y, BN);
                    if (OUTH)
                        g_hh[n * (DO / 2) + (col >> 1)] = f2h(v0, v1);
                    else
                        *(float2*)&g_h[n * DO + col] = make_float2(v0, v1);
                } else {
                    g_hh[n * (DO / 2) + (col >> 1)] = f2h(c0, c1);
                }
            }
        }
    }
}

// ---------------- pool encoding ---------------------------------------------
__device__ __forceinline__ unsigned fenc(float x) {
    unsigned u = __float_as_uint(x);
    return (u & 0x80000000u) ? ~u : (u | 0x80000000u);
}
__device__ __forceinline__ float fdec(unsigned u) {
    return (u & 0x80000000u) ? __uint_as_float(u & 0x7fffffffu) : __uint_as_float(~u);
}

// ---------------- L5: aggregate (half) + bias + BN + GELU + pool ------------
__global__ void __launch_bounds__(256) k_aggr_post(const float* __restrict__ b,
                                                   const float* __restrict__ gam,
                                                   const float* __restrict__ bet,
                                                   const int* __restrict__ batch) {
    int lane = threadIdx.x & 31;
    int warp = threadIdx.x >> 5;
    int n = blockIdx.x * 8 + warp;
    if (n >= NN) return;
    float2 f = h2f(g_hh[n * 32 + lane]);
    float ax = f.x, ay = f.y, bx = 0.f, by = 0.f;
    int e = g_off[n];
    int r1 = e + g_degi[n];
    for (; e + 3 < r1; e += 4) {
        unsigned v0 = __ldg(&g_hh[g_csrc[e] * 32 + lane]);
        unsigned v1 = __ldg(&g_hh[g_csrc[e + 1] * 32 + lane]);
        unsigned v2 = __ldg(&g_hh[g_csrc[e + 2] * 32 + lane]);
        unsigned v3 = __ldg(&g_hh[g_csrc[e + 3] * 32 + lane]);
        float2 f0 = h2f(v0), f1 = h2f(v1), f2 = h2f(v2), f3 = h2f(v3);
        ax += f0.x + f2.x; ay += f0.y + f2.y;
        bx += f1.x + f3.x; by += f1.y + f3.y;
    }
    for (; e < r1; e++) {
        float2 f0 = h2f(__ldg(&g_hh[g_csrc[e] * 32 + lane]));
        ax += f0.x; ay += f0.y;
    }
    float di = g_dinv[n];
    int gb = batch[n];
    float2 bb = __ldg(&((const float2*)b)[lane]);
    float2 gg = __ldg(&((const float2*)gam)[lane]);
    float2 be = __ldg(&((const float2*)bet)[lane]);
    float v0 = gelu_bn(di * (ax + bx), bb.x, gg.x, be.x, true);
    float v1 = gelu_bn(di * (ay + by), bb.y, gg.y, be.y, true);
    atomicMax(&g_pool[gb * 64 + 2 * lane + 0], fenc(v0));
    atomicMax(&g_pool[gb * 64 + 2 * lane + 1], fenc(v1));
}

// ---------------- MLP head --------------------------------------------------
__global__ void __launch_bounds__(256) k_head(const float* __restrict__ lw1,
                                              const float* __restrict__ lb1,
                                              const float* __restrict__ lw2,
                                              const float* __restrict__ lb2,
                                              float* __restrict__ out) {
    int g = blockIdx.x * blockDim.x + threadIdx.x;
    if (g < GG) {
        float p[64];
#pragma unroll
        for (int d = 0; d < 64; d++) p[d] = fdec(g_pool[g * 64 + d]);
        float o0 = lb2[0];
        float o1 = lb2[1];
#pragma unroll
        for (int j = 0; j < 10; j++) {
            float hj = lb1[j];
#pragma unroll
            for (int d = 0; d < 64; d++) hj += p[d] * lw1[d * 10 + j];
            o0 += hj * lw2[j * 2 + 0];
            o1 += hj * lw2[j * 2 + 1];
        }
        out[g * 2 + 0] = o0;
        out[g * 2 + 1] = o1;
    }
}

extern "C" void kernel_launch(void* const* d_in, const int* in_sizes, int n_in,
                              void* d_out, int out_size) {
    const float* x = (const float*)d_in[0];
    const int* ei = (const int*)d_in[1];
    const int* src = ei;
    const int* dst = ei + EE;
    const int* batch = (const int*)d_in[2];
    const float* W1 = (const float*)d_in[3];
    const float* b1 = (const float*)d_in[4];
    const float* W2 = (const float*)d_in[5];
    const float* b2 = (const float*)d_in[6];
    const float* W3 = (const float*)d_in[7];
    const float* b3 = (const float*)d_in[8];
    const float* W4 = (const float*)d_in[9];
    const float* b4 = (const float*)d_in[10];
    const float* W5 = (const float*)d_in[11];
    const float* b5 = (const float*)d_in[12];
    const float* g1 = (const float*)d_in[13];
    const float* be1 = (const float*)d_in[14];
    const float* g2 = (const float*)d_in[15];
    const float* be2 = (const float*)d_in[16];
    const float* g3 = (const float*)d_in[17];
    const float* be3 = (const float*)d_in[18];
    const float* lw1 = (const float*)d_in[19];
    const float* lb1 = (const float*)d_in[20];
    const float* lw2 = (const float*)d_in[21];
    const float* lb2 = (const float*)d_in[22];
    float* out = (float*)d_out;

    float* aptr = nullptr;
    float* hptr = nullptr;
    __half* whptr = nullptr;
    cudaGetSymbolAddress((void**)&aptr, g_a);
    cudaGetSymbolAddress((void**)&hptr, g_h);
    cudaGetSymbolAddress((void**)&whptr, g_wh);

    // CSR build + weight preconversion
    k_zero<<<(NN + 255) / 256, 256>>>();
    k_deg<<<(EE + 255) / 256, 256>>>(dst);
    k_prep<<<(NN + 255) / 256, 256>>>(x);
    k_fill<<<(EE + 255) / 256, 256>>>(src, dst);
    k_wconv<<<144, 256>>>(W2, W3, W4, W5);

    const int GB = (NN + 127) / 128;

    // L1: aggregate (DI=2, fp32) then tiny GEMM 2->64 + BN + GELU + dinv -> half
    k_aggr_pre2<<<(NN + 255) / 256, 256>>>();
    k_l1<<<(NN + 7) / 8, 256>>>(W1, b1, g1, be1);
    // L2: aggregate(64, half) then HMMA GEMM 64->64 + GELU + dinv -> half
    k_aggr64h<<<(NN + 7) / 8, 256>>>(aptr);
    k_mma<64, 64, true, false, true><<<GB, 256>>>(aptr, whptr + 0, b2, nullptr, nullptr);
    // L3: aggregate(64, half) then HMMA GEMM 64->128 + BN + GELU + dinv -> half
    k_aggr64h<<<(NN + 7) / 8, 256>>>(aptr);
    k_mma<64, 128, true, true, true><<<GB, 256>>>(aptr, whptr + 4096, b3, g2, be2);
    // L4: aggregate(128, half) then HMMA GEMM 128->128 + GELU + dinv -> fp32
    k_aggr128h<<<(NN + 7) / 8, 256>>>();
    k_mma<128, 128, true, false, false><<<GB, 256>>>(aptr, whptr + 12288, b4, nullptr, nullptr);
    // L5: HMMA GEMM 128->64 (raw acc -> half) then aggregate+bias+BN+GELU+pool
    k_mma<128, 64, false, false, true><<<GB, 256>>>(hptr, whptr + 28672, nullptr, nullptr, nullptr);
    k_aggr_post<<<(NN + 7) / 8, 256>>>(b5, g3, be3, batch);

    k_head<<<2, 256>>>(lw1, lb1, lw2, lb2, out);
}